// round 12
// baseline (speedup 1.0000x reference)
#include <cuda_runtime.h>

#define LOG2E 1.4426950408889634f
#define LN2   0.6931471805599453f
#define CHUNK 64
#define MAXC  16         // ceil(1023/64)
#define NPK   17         // 0..7 = q-pairs (backward), 8..15 = r-pairs (forward), 16 = gathers

__device__ float g_qv[1024][MAXC][64];
__device__ float g_rv[1024][MAXC - 1][64];
__device__ float g_qoff[1024][MAXC];
__device__ float g_roff[1024][MAXC - 1];
__device__ float g_seqs[1024];
__device__ float g_partial[1024];
__device__ unsigned int g_done[1024];   // zero-init; self-resetting
__device__ unsigned int g_count = 0;

static __device__ __forceinline__ float ex2f_(float x) {
    float y; asm("ex2.approx.ftz.f32 %0, %1;" : "=f"(y) : "f"(x)); return y;
}
static __device__ __forceinline__ float lg2f_(float x) {
    float y; asm("lg2.approx.ftz.f32 %0, %1;" : "=f"(y) : "f"(x)); return y;
}
static __device__ __forceinline__ unsigned long long pack2_(float lo, float hi) {
    unsigned long long d;
    asm("mov.b64 %0, {%1, %2};" : "=l"(d) : "f"(lo), "f"(hi));
    return d;
}
static __device__ __forceinline__ unsigned long long fma2_(unsigned long long a,
                                                           unsigned long long b,
                                                           unsigned long long c) {
    unsigned long long d;
    asm("fma.rn.f32x2 %0, %1, %2, %3;" : "=l"(d) : "l"(a), "l"(b), "l"(c));
    return d;
}
static __device__ __forceinline__ unsigned long long addx2_(unsigned long long a,
                                                            unsigned long long b) {
    unsigned long long d;
    asm("add.rn.f32x2 %0, %1, %2;" : "=l"(d) : "l"(a), "l"(b));
    return d;
}
static __device__ __forceinline__ void unpack2_(unsigned long long v, float& lo, float& hi) {
    asm("mov.b64 {%0, %1}, %2;" : "=f"(lo), "=f"(hi) : "l"(v));
}
static __device__ __forceinline__ float wredsum_(float v) {
#pragma unroll
    for (int m = 16; m > 0; m >>= 1) v += __shfl_xor_sync(0xffffffffu, v, m);
    return v;
}

// Full 64-wide contraction for the two owned states (2*lane, 2*lane+1).
// 64 FFMA2 per call. Reads all of BUF via broadcast LDS.128.
#define MACF(BUF, SO, SP)                                                   \
    {                                                                       \
        const ulonglong2* wv_ = (const ulonglong2*)(BUF);                   \
        unsigned long long o0_=0ull, o1_=0ull, p0_=0ull, p1_=0ull;          \
        _Pragma("unroll")                                                   \
        for (int k_ = 0; k_ < 16; k_++) {                                   \
            ulonglong2 q_ = wv_[k_];                                        \
            o0_ = fma2_(q_.x, eO[2*k_],     o0_);                           \
            o1_ = fma2_(q_.y, eO[2*k_ + 1], o1_);                           \
            p0_ = fma2_(q_.x, eP[2*k_],     p0_);                           \
            p1_ = fma2_(q_.y, eP[2*k_ + 1], p1_);                           \
        }                                                                   \
        float lo_, hi_;                                                     \
        unpack2_(addx2_(o0_, o1_), lo_, hi_); SO = lo_ + hi_;               \
        unpack2_(addx2_(p0_, p1_), lo_, hi_); SP = lo_ + hi_;               \
    }

// -------- forward bodies: MAC(old w) -> sync -> write new w -> sync --------
#define FPAIR(UU, PB)                                                       \
    {                                                                       \
        float pAO_, pAP_, pBO_, pBP_;                                       \
        if (PB) {                                                           \
            float lA_ = lg2f_(dshA[1]); loffA += lA_;                       \
            pAO_ = ex2f_(fmaf(pfA[UU].x, LOG2E, -lA_));                     \
            pAP_ = ex2f_(fmaf(pfA[UU].y, LOG2E, -lA_));                     \
            float lB_ = lg2f_(dshB[1]); loffB += lB_;                       \
            pBO_ = ex2f_(fmaf(pfB[UU].x, LOG2E, -lB_));                     \
            pBP_ = ex2f_(fmaf(pfB[UU].y, LOG2E, -lB_));                     \
        } else {                                                            \
            pAO_ = ex2f_(pfA[UU].x * LOG2E); pAP_ = ex2f_(pfA[UU].y * LOG2E);\
            pBO_ = ex2f_(pfB[UU].x * LOG2E); pBP_ = ex2f_(pfB[UU].y * LOG2E);\
        }                                                                   \
        pfA[UU] = *(const float2*)(potc + offA); offA = min(offA + 256, offhiA);\
        pfB[UU] = *(const float2*)(potc + offB); offB = min(offB + 256, offhiB);\
        float sAO_, sAP_, sBO_, sBP_;                                       \
        MACF(wshA, sAO_, sAP_)                                              \
        MACF(wshB, sBO_, sBP_)                                              \
        __syncwarp();                                                       \
        float vAO_ = sAO_*pAO_, vAP_ = sAP_*pAP_;                           \
        float vBO_ = sBO_*pBO_, vBP_ = sBP_*pBP_;                           \
        *(float2*)&wshA[lane2] = make_float2(vAO_, vAP_);                   \
        *(float2*)&wshB[lane2] = make_float2(vBO_, vBP_);                   \
        if (lane == 0) { dshA[PB] = vAO_; dshB[PB] = vBO_; }                \
        __syncwarp();                                                       \
    }

#define FSING(UU, PB)                                                       \
    {                                                                       \
        float pAO_, pAP_;                                                   \
        if (PB) {                                                           \
            float lA_ = lg2f_(dshA[1]); loffA += lA_;                       \
            pAO_ = ex2f_(fmaf(pfA[UU].x, LOG2E, -lA_));                     \
            pAP_ = ex2f_(fmaf(pfA[UU].y, LOG2E, -lA_));                     \
        } else {                                                            \
            pAO_ = ex2f_(pfA[UU].x * LOG2E); pAP_ = ex2f_(pfA[UU].y * LOG2E);\
        }                                                                   \
        pfA[UU] = *(const float2*)(potc + offA); offA = min(offA + 256, offhiA);\
        float sAO_, sAP_;                                                   \
        MACF(wshA, sAO_, sAP_)                                              \
        __syncwarp();                                                       \
        float vAO_ = sAO_*pAO_, vAP_ = sAP_*pAP_;                           \
        *(float2*)&wshA[lane2] = make_float2(vAO_, vAP_);                   \
        if (lane == 0) dshA[PB] = vAO_;                                     \
        __syncwarp();                                                       \
    }

// forward tail (chain A, always-norm, fresh tq regs, slot ping-pong tp)
#define FTAIL(TQ)                                                           \
    {                                                                       \
        float lD_ = lg2f_(dshA[tp ^ 1]); loffA += lD_;                      \
        float pO_ = ex2f_(fmaf(TQ.x, LOG2E, -lD_));                         \
        float pP_ = ex2f_(fmaf(TQ.y, LOG2E, -lD_));                         \
        TQ = *(const float2*)(potc + offT); offT = min(offT + 256, offhiA); \
        float sO_, sP_;                                                     \
        MACF(wshA, sO_, sP_)                                                \
        __syncwarp();                                                       \
        float vO_ = sO_*pO_, vP_ = sP_*pP_;                                 \
        *(float2*)&wshA[lane2] = make_float2(vO_, vP_);                     \
        if (lane == 0) dshA[tp] = vO_;                                      \
        __syncwarp();                                                       \
        tp ^= 1;                                                            \
    }

// -------- backward bodies: write y = p*x -> sync -> MAC -> sync --------
#define BPAIR(UU, PB)                                                       \
    {                                                                       \
        float pAO_, pAP_, pBO_, pBP_;                                       \
        if (PB) {                                                           \
            float lA_ = lg2f_(dshA[(PB)^1]); loffA += lA_;                  \
            pAO_ = ex2f_(fmaf(pfA[UU].x, LOG2E, -lA_));                     \
            pAP_ = ex2f_(fmaf(pfA[UU].y, LOG2E, -lA_));                     \
            float lB_ = lg2f_(dshB[(PB)^1]); loffB += lB_;                  \
            pBO_ = ex2f_(fmaf(pfB[UU].x, LOG2E, -lB_));                     \
            pBP_ = ex2f_(fmaf(pfB[UU].y, LOG2E, -lB_));                     \
        } else {                                                            \
            pAO_ = ex2f_(pfA[UU].x * LOG2E); pAP_ = ex2f_(pfA[UU].y * LOG2E);\
            pBO_ = ex2f_(pfB[UU].x * LOG2E); pBP_ = ex2f_(pfB[UU].y * LOG2E);\
        }                                                                   \
        pfA[UU] = *(const float2*)(potc + offA); offA = max(offA - 256, offloA);\
        pfB[UU] = *(const float2*)(potc + offB); offB = max(offB - 256, offloB);\
        float yAO_ = xAO*pAO_, yAP_ = xAP*pAP_;                             \
        float yBO_ = xBO*pBO_, yBP_ = xBP*pBP_;                             \
        *(float2*)&wshA[lane2] = make_float2(yAO_, yAP_);                   \
        *(float2*)&wshB[lane2] = make_float2(yBO_, yBP_);                   \
        if (lane == 0) { dshA[PB] = yAO_; dshB[PB] = yBO_; }                \
        __syncwarp();                                                       \
        MACF(wshA, xAO, xAP)                                                \
        MACF(wshB, xBO, xBP)                                                \
        __syncwarp();                                                       \
    }

#define BSING(UU, PB)                                                       \
    {                                                                       \
        float pAO_, pAP_;                                                   \
        if (PB) {                                                           \
            float lA_ = lg2f_(dshA[(PB)^1]); loffA += lA_;                  \
            pAO_ = ex2f_(fmaf(pfA[UU].x, LOG2E, -lA_));                     \
            pAP_ = ex2f_(fmaf(pfA[UU].y, LOG2E, -lA_));                     \
        } else {                                                            \
            pAO_ = ex2f_(pfA[UU].x * LOG2E); pAP_ = ex2f_(pfA[UU].y * LOG2E);\
        }                                                                   \
        pfA[UU] = *(const float2*)(potc + offA); offA = max(offA - 256, offloA);\
        float yAO_ = xAO*pAO_, yAP_ = xAP*pAP_;                             \
        *(float2*)&wshA[lane2] = make_float2(yAO_, yAP_);                   \
        if (lane == 0) dshA[PB] = yAO_;                                     \
        __syncwarp();                                                       \
        MACF(wshA, xAO, xAP)                                                \
        __syncwarp();                                                       \
    }

#define BTAIL(TQ)                                                           \
    {                                                                       \
        float lD_ = lg2f_(dshA[tp ^ 1]); loffA += lD_;                      \
        float pO_ = ex2f_(fmaf(TQ.x, LOG2E, -lD_));                         \
        float pP_ = ex2f_(fmaf(TQ.y, LOG2E, -lD_));                         \
        TQ = *(const float2*)(potc + offT); offT = max(offT - 256, offloA); \
        float yO_ = xAO*pO_, yP_ = xAP*pP_;                                 \
        *(float2*)&wshA[lane2] = make_float2(yO_, yP_);                     \
        if (lane == 0) dshA[tp] = yO_;                                      \
        __syncwarp();                                                       \
        MACF(wshA, xAO, xAP)                                                \
        __syncwarp();                                                       \
        tp ^= 1;                                                            \
    }

// One CTA = ONE WARP per (batch, task-pair). Lane owns states (2*lane, 2*lane+1).
__global__ __launch_bounds__(32, 8) void crf_all_kernel(
    const float* __restrict__ pot,     // [B, T, 64]
    const int*   __restrict__ tags,    // [B, T]
    const int*   __restrict__ seqlen,  // [B]
    const float* __restrict__ K,       // [64, 64]
    const float* __restrict__ sw,      // [B]
    float*       __restrict__ out,
    int T, int B)
{
    const int b     = blockIdx.x / NPK;
    const int k     = blockIdx.x % NPK;
    const int lane  = threadIdx.x;
    const int lane2 = lane << 1;

    int L = seqlen[b];
    if (L > T) L = T;
    if (L < 1) L = 1;
    const int M  = L - 1;
    const int nc = (M + CHUNK - 1) / CHUNK;

    const float* potb = pot + (size_t)b * T * 64;
    const char*  potc = (const char*)potb;

    __shared__ __align__(16) float wshA[64];
    __shared__ __align__(16) float wshB[64];
    __shared__ float dshA[2], dshB[2];

    int cnt = 1;

    if (k == NPK - 1) {
        // ================= sequence-score gathers =================
        const int* tagb = tags + (size_t)b * T;
        float acc = 0.f;
        for (int t = lane; t < T; t += 32) {
            if (t < L) {
                int tg = tagb[t];
                acc += __ldg(potb + (size_t)t * 64 + tg);
                if (t >= 1) {
                    int tgp = tagb[t - 1];
                    acc += __ldg(K + tgp * 64 + tg);
                }
            }
        }
        acc = wredsum_(acc);
        if (lane == 0) g_seqs[b] = acc;
    } else {
        const bool is_q = (k < 8);
        const int  kp   = is_q ? k : (k - 8);
        const int  cA   = 2 * kp + 1;
        const int  cB   = 2 * kp + 2;
        const int  cmax = is_q ? nc : (nc - 1);
        const bool validA = (cA <= cmax);
        const bool validB = (cB <= cmax);
        if (!validA) return;          // no arrival
        cnt = validB ? 2 : 1;

        const int aA = (cA - 1) * CHUNK + 1, bendA = min(cA * CHUNK, M);
        const int aB = (cB - 1) * CHUNK + 1, bendB = min(cB * CHUNK, M);
        const int nsA = bendA - aA + 1;
        const int nsB = validB ? (bendB - aB + 1) : 0;
        const int s8 = lane << 3;
        const int offloA = aA * 256 + s8, offhiA = bendA * 256 + s8;
        const int offloB = aB * 256 + s8, offhiB = bendB * 256 + s8;

        // E registers: full rows (backward) or columns (forward) for both states.
        unsigned long long eO[32], eP[32];
        if (is_q) {
            const float4* krO = (const float4*)(K + lane2 * 64);
            const float4* krP = (const float4*)(K + (lane2 + 1) * 64);
#pragma unroll
            for (int m = 0; m < 16; m++) {
                float4 vO = krO[m], vP = krP[m];
                eO[2*m]   = pack2_(ex2f_(vO.x * LOG2E), ex2f_(vO.y * LOG2E));
                eO[2*m+1] = pack2_(ex2f_(vO.z * LOG2E), ex2f_(vO.w * LOG2E));
                eP[2*m]   = pack2_(ex2f_(vP.x * LOG2E), ex2f_(vP.y * LOG2E));
                eP[2*m+1] = pack2_(ex2f_(vP.z * LOG2E), ex2f_(vP.w * LOG2E));
            }
        } else {
#pragma unroll
            for (int m = 0; m < 16; m++) {
                int r = 4 * m;
                eO[2*m]   = pack2_(ex2f_(K[r * 64 + lane2]       * LOG2E),
                                   ex2f_(K[(r + 1) * 64 + lane2] * LOG2E));
                eO[2*m+1] = pack2_(ex2f_(K[(r + 2) * 64 + lane2] * LOG2E),
                                   ex2f_(K[(r + 3) * 64 + lane2] * LOG2E));
                eP[2*m]   = pack2_(ex2f_(K[r * 64 + lane2 + 1]       * LOG2E),
                                   ex2f_(K[(r + 1) * 64 + lane2 + 1] * LOG2E));
                eP[2*m+1] = pack2_(ex2f_(K[(r + 2) * 64 + lane2 + 1] * LOG2E),
                                   ex2f_(K[(r + 3) * 64 + lane2 + 1] * LOG2E));
            }
        }

        float loffA = 0.f, loffB = 0.f;
        float2 pfA[4], pfB[4];
        int tp = 0;

        if (lane == 0) { dshA[0] = dshA[1] = 1.0f; dshB[0] = dshB[1] = 1.0f; }

        if (is_q) {
            // ======== backward chains: q_c = Pi_{t=a..bend}(E diag p_t) 1 ========
            float xAO = 1.0f, xAP = 1.0f, xBO = 1.0f, xBP = 1.0f;
#pragma unroll
            for (int u = 0; u < 4; u++) {
                int rA = bendA - u; if (rA < aA) rA = aA;
                pfA[u] = *(const float2*)(potc + rA * 256 + s8);
            }
            int offA = (bendA - 4) * 256 + s8; if (offA < offloA) offA = offloA;
            int offB = offloB;
            if (validB) {
#pragma unroll
                for (int u = 0; u < 4; u++) {
                    int rB = bendB - u; if (rB < aB) rB = aB;
                    pfB[u] = *(const float2*)(potc + rB * 256 + s8);
                }
                offB = (bendB - 4) * 256 + s8; if (offB < offloB) offB = offloB;
            }
            __syncwarp();

            if (validB) {
                int n4 = nsB >> 2;
                for (int it = 0; it < n4; it++) {
                    BPAIR(0, 0) BPAIR(1, 1) BPAIR(2, 0) BPAIR(3, 1)
                }
                int rem = nsB & 3;
                if (rem > 0) BPAIR(0, 0)
                if (rem > 1) BPAIR(1, 1)
                if (rem > 2) BPAIR(2, 0)

                *(float2*)&g_qv[b][cB - 1][lane2] = make_float2(xBO, xBP);
                if (lane == 0) g_qoff[b][cB - 1] = loffB;

                int rem2 = nsA - nsB;
                if (rem2 > 0) {
                    int r0 = bendA - nsB;
                    int r1 = r0 - 1; if (r1 < aA) r1 = aA;
                    float2 tq0 = *(const float2*)(potc + r0 * 256 + s8);
                    float2 tq1 = *(const float2*)(potc + r1 * 256 + s8);
                    int offT = (r0 - 2) * 256 + s8; if (offT < offloA) offT = offloA;
                    int s = 0;
                    for (; s + 2 <= rem2; s += 2) { BTAIL(tq0) BTAIL(tq1) }
                    if (s < rem2) BTAIL(tq0)
                }
            } else {
                int n4 = nsA >> 2;
                for (int it = 0; it < n4; it++) {
                    BSING(0, 0) BSING(1, 1) BSING(2, 0) BSING(3, 1)
                }
                int rem = nsA & 3;
                if (rem > 0) BSING(0, 0)
                if (rem > 1) BSING(1, 1)
                if (rem > 2) BSING(2, 0)
            }

            *(float2*)&g_qv[b][cA - 1][lane2] = make_float2(xAO, xAP);
            if (lane == 0) g_qoff[b][cA - 1] = loffA;
        } else {
            // ======== forward chains: r_c^T = 1^T Pi_{t=a..bend}(E diag p_t) ========
            *(float2*)&wshA[lane2] = make_float2(1.0f, 1.0f);
            *(float2*)&wshB[lane2] = make_float2(1.0f, 1.0f);
#pragma unroll
            for (int u = 0; u < 4; u++) {
                int rA = aA + u; if (rA > bendA) rA = bendA;
                pfA[u] = *(const float2*)(potc + rA * 256 + s8);
            }
            int offA = (aA + 4) * 256 + s8; if (offA > offhiA) offA = offhiA;
            int offB = offloB;
            if (validB) {
#pragma unroll
                for (int u = 0; u < 4; u++) {
                    int rB = aB + u; if (rB > bendB) rB = bendB;
                    pfB[u] = *(const float2*)(potc + rB * 256 + s8);
                }
                offB = (aB + 4) * 256 + s8; if (offB > offhiB) offB = offhiB;
            }
            __syncwarp();

            if (validB) {
                int n4 = nsB >> 2;
                for (int it = 0; it < n4; it++) {
                    FPAIR(0, 0) FPAIR(1, 1) FPAIR(2, 0) FPAIR(3, 1)
                }
                int rem = nsB & 3;
                if (rem > 0) FPAIR(0, 0)
                if (rem > 1) FPAIR(1, 1)
                if (rem > 2) FPAIR(2, 0)

                *(float2*)&g_rv[b][cB - 1][lane2] = *(float2*)&wshB[lane2];
                if (lane == 0) g_roff[b][cB - 1] = loffB;

                int rem2 = nsA - nsB;
                if (rem2 > 0) {
                    int r0 = aA + nsB;
                    int r1 = r0 + 1; if (r1 > bendA) r1 = bendA;
                    float2 tq0 = *(const float2*)(potc + r0 * 256 + s8);
                    float2 tq1 = *(const float2*)(potc + r1 * 256 + s8);
                    int offT = (r0 + 2) * 256 + s8; if (offT > offhiA) offT = offhiA;
                    int s = 0;
                    for (; s + 2 <= rem2; s += 2) { FTAIL(tq0) FTAIL(tq1) }
                    if (s < rem2) FTAIL(tq0)
                }
            } else {
                int n4 = nsA >> 2;
                for (int it = 0; it < n4; it++) {
                    FSING(0, 0) FSING(1, 1) FSING(2, 0) FSING(3, 1)
                }
                int rem = nsA & 3;
                if (rem > 0) FSING(0, 0)
                if (rem > 1) FSING(1, 1)
                if (rem > 2) FSING(2, 0)
            }

            *(float2*)&g_rv[b][cA - 1][lane2] = *(float2*)&wshA[lane2];
            if (lane == 0) g_roff[b][cA - 1] = loffA;
        }
    }

    // ================= arrival + inline stitch (last task of batch) =================
    __threadfence();
    const unsigned int ntasks = 1u + (unsigned)nc + (unsigned)(nc > 0 ? nc - 1 : 0);
    unsigned int old = 0;
    if (lane == 0) old = atomicAdd(&g_done[b], (unsigned)cnt);
    old = __shfl_sync(0xffffffffu, old, 0);
    if (old + (unsigned)cnt != ntasks) return;

    if (lane == 0) g_done[b] = 0;    // reset for graph replay
    __threadfence();

    float2 p0;
    p0.x = ex2f_(potb[lane2]     * LOG2E);
    p0.y = ex2f_(potb[lane2 + 1] * LOG2E);

    float log2A;
    if (nc == 0) {
        log2A = lg2f_(wredsum_(p0.x + p0.y));
    } else {
        float2 q0 = *(const float2*)&g_qv[b][0][lane2];
        float d1 = wredsum_(p0.x * q0.x + p0.y * q0.y);
        log2A = lg2f_(d1) + g_qoff[b][0];
        for (int cc = 2; cc <= nc; cc++) {
            float2 rv = *(const float2*)&g_rv[b][cc - 2][lane2];
            float2 qc = *(const float2*)&g_qv[b][cc - 1][lane2];
            float2 qm = *(const float2*)&g_qv[b][cc - 2][lane2];
            float d   = wredsum_(rv.x * qc.x + rv.y * qc.y);
            float sig = wredsum_(qm.x + qm.y);
            log2A += lg2f_(d) + g_roff[b][cc - 2] + g_qoff[b][cc - 1]
                   - lg2f_(sig) - g_qoff[b][cc - 2];
        }
    }

    if (lane == 0) {
        g_partial[b] = -(g_seqs[b] - log2A * LN2) * sw[b];
        __threadfence();
    }
    __syncwarp();

    unsigned int o2 = 0;
    if (lane == 0) o2 = atomicAdd(&g_count, 1);
    o2 = __shfl_sync(0xffffffffu, o2, 0);
    if (o2 == (unsigned)B - 1) {
        if (lane == 0) { g_count = 0; __threadfence(); }
        __syncwarp();
        float tot = 0.f;
        for (int i = lane; i < B; i += 32) tot += g_partial[i];
        tot = wredsum_(tot);
        if (lane == 0) *out = tot / (float)B;
    }
}

extern "C" void kernel_launch(void* const* d_in, const int* in_sizes, int n_in,
                              void* d_out, int out_size) {
    const float* pot    = (const float*)d_in[0];
    const int*   tags   = (const int*)d_in[1];
    const int*   seqlen = (const int*)d_in[2];
    const float* K      = (const float*)d_in[3];
    const float* sw     = (const float*)d_in[4];

    int B = in_sizes[2];            // sequence_length element count
    int T = in_sizes[1] / B;        // tags is [B, T]

    crf_all_kernel<<<B * NPK, 32>>>(pot, tags, seqlen, K, sw, (float*)d_out, T, B);
}